// round 2
// baseline (speedup 1.0000x reference)
#include <cuda_runtime.h>
#include <cuda_bf16.h>

#define N_UE 100000
#define N_AP 10000
#define N_E  1600000
#define DD   64
#define HH   128

// ---------------- scratch (device globals; no allocation allowed) ----------
__device__ float g_ueproj[(size_t)N_UE * HH];      // ue_hid @ W1a[64:] + b1a
__device__ float g_agg[(size_t)N_AP * HH];         // segment_sum(relu(...))
__device__ int   g_cnt[N_AP];
__device__ int   g_cursor[N_AP];
__device__ int   g_perm[N_E];
__device__ int   g_ssrc[N_E];
__device__ int   g_sdst[N_E];
__device__ __nv_bfloat16 g_wt_hi[HH * DD];         // W1a[:64] transposed [n][k], bf16 hi
__device__ __nv_bfloat16 g_wt_lo[HH * DD];         // residual lo plane

// ---------------- small setup kernels --------------------------------------
__global__ void k_zero() {
    int i = blockIdx.x * 256 + threadIdx.x;   // grid 5000*256 = 1.28M = N_AP*HH
    if (i < N_AP * HH) g_agg[i] = 0.f;
    if (i < N_AP) g_cnt[i] = 0;
}

__global__ void k_hist(const int* __restrict__ dst) {
    int i = blockIdx.x * 256 + threadIdx.x;
    if (i < N_E) atomicAdd(&g_cnt[dst[i]], 1);
}

// exclusive prefix over 10000 bins -> g_cursor. One block of 1024 threads.
__global__ void k_scan() {
    __shared__ int buf[1024];
    int t = threadIdx.x;
    int local[16];
    int s = 0;
    if (t < 625) {
        #pragma unroll
        for (int j = 0; j < 16; j++) { local[j] = s; s += g_cnt[t * 16 + j]; }
    }
    buf[t] = s;
    __syncthreads();
    int own = s;
    for (int off = 1; off < 1024; off <<= 1) {
        int v = 0;
        if (t >= off) v = buf[t - off];
        __syncthreads();
        buf[t] += v;
        __syncthreads();
    }
    int excl = buf[t] - own;
    if (t < 625) {
        #pragma unroll
        for (int j = 0; j < 16; j++) g_cursor[t * 16 + j] = excl + local[j];
    }
}

__global__ void k_scatter(const int* __restrict__ src, const int* __restrict__ dst) {
    int i = blockIdx.x * 256 + threadIdx.x;
    if (i < N_E) {
        int d = dst[i];
        int p = atomicAdd(&g_cursor[d], 1);
        g_perm[p] = i;
        g_sdst[p] = d;
        g_ssrc[p] = src[i];
    }
}

__global__ void k_prep_w(const float* __restrict__ W1a) {
    int j = blockIdx.x * 256 + threadIdx.x;
    if (j < HH * DD) {
        int n = j >> 6, k = j & 63;                 // Wt[n][k] = W1a[k][n], k<64
        float v = W1a[k * HH + n];
        __nv_bfloat16 h = __float2bfloat16(v);
        g_wt_hi[j] = h;
        g_wt_lo[j] = __float2bfloat16(v - __bfloat162float(h));
    }
}

// ---------------- ue projection: g_ueproj = ue_hid @ W1a[64:128] + b1a -----
__global__ void __launch_bounds__(256) k_ueproj(
    const float* __restrict__ ue_hid, const float* __restrict__ W1a,
    const float* __restrict__ b1a)
{
    __shared__ float us[64][64];
    int t = threadIdx.x;
    int rbase = blockIdx.x * 64;

    // load 64 rows of ue_hid (guarded)
    for (int f = t; f < 1024; f += 256) {
        int row = f >> 4, c4 = f & 15;
        float4 v = make_float4(0.f, 0.f, 0.f, 0.f);
        if (rbase + row < N_UE)
            v = *(const float4*)(ue_hid + (size_t)(rbase + row) * DD + c4 * 4);
        *(float4*)(&us[row][c4 * 4]) = v;
    }

    int c = t & 127;
    int rh = t >> 7;
    float wc[64];
    #pragma unroll 8
    for (int k = 0; k < 64; k++) wc[k] = W1a[(64 + k) * HH + c];
    float bb = b1a[c];
    __syncthreads();

    for (int i = 0; i < 32; i++) {
        int r = rh * 32 + i;
        int gr = rbase + r;
        if (gr >= N_UE) break;          // uniform per warp
        float acc = bb;
        #pragma unroll
        for (int k = 0; k < 64; k++) acc += us[r][k] * wc[k];
        g_ueproj[(size_t)gr * HH + c] = acc;
    }
}

// ---------------- main edge kernel: bf16-split mma + segmented reduce ------
__device__ __forceinline__ void mma_bf16(float c[4],
    unsigned a0, unsigned a1, unsigned a2, unsigned a3,
    unsigned b0, unsigned b1)
{
    asm volatile(
        "mma.sync.aligned.m16n8k16.row.col.f32.bf16.bf16.f32 "
        "{%0,%1,%2,%3}, {%4,%5,%6,%7}, {%8,%9}, {%0,%1,%2,%3};\n"
        : "+f"(c[0]), "+f"(c[1]), "+f"(c[2]), "+f"(c[3])
        : "r"(a0), "r"(a1), "r"(a2), "r"(a3), "r"(b0), "r"(b1));
}

#define ASTR 72           // padded smem stride (bf16 elems) -> conflict-free
#define SMEM_MAIN (4 * 128 * ASTR * 2)   // 73728 B (Hs reuses this region)

__global__ void __launch_bounds__(256, 2) k_main(const float* __restrict__ edge_hid)
{
    extern __shared__ char sraw[];
    __nv_bfloat16* Ah = (__nv_bfloat16*)sraw;          // [128][72]
    __nv_bfloat16* Al = Ah + 128 * ASTR;
    __nv_bfloat16* Bh = Al + 128 * ASTR;               // Wt [n=128][k=64]
    __nv_bfloat16* Bl = Bh + 128 * ASTR;
    float* Hs = (float*)sraw;                          // [128][132], reused after mma
    __shared__ int s_src[128];
    __shared__ int s_dst[128];

    int t = threadIdx.x;
    int base = blockIdx.x * 128;

    if (t < 128) { s_src[t] = g_ssrc[base + t]; s_dst[t] = g_sdst[base + t]; }

    // stage weights (hi/lo planes) into padded smem
    for (int j = t; j < HH * DD; j += 256) {
        int n = j >> 6, k = j & 63;
        Bh[n * ASTR + k] = g_wt_hi[j];
        Bl[n * ASTR + k] = g_wt_lo[j];
    }

    // gather + split 128 edge rows: thread -> (row = t>>1, half = t&1)
    {
        int row = t >> 1, half = t & 1;
        int e = g_perm[base + row];
        const float4* src4 = (const float4*)(edge_hid + (size_t)e * DD + half * 32);
        int sb = row * ASTR + half * 32;
        #pragma unroll
        for (int q = 0; q < 8; q++) {
            float4 v = src4[q];
            float xs[4] = {v.x, v.y, v.z, v.w};
            #pragma unroll
            for (int u = 0; u < 4; u++) {
                __nv_bfloat16 h = __float2bfloat16(xs[u]);
                Ah[sb + q * 4 + u] = h;
                Al[sb + q * 4 + u] = __float2bfloat16(xs[u] - __bfloat162float(h));
            }
        }
    }
    __syncthreads();

    int w = t >> 5, l = t & 31;
    int g = l >> 2, q4 = l & 3;
    int ar = w * 16 + g;                 // warp w owns rows [16w,16w+16)

    float C[16][4];
    #pragma unroll
    for (int nf = 0; nf < 16; nf++) { C[nf][0] = C[nf][1] = C[nf][2] = C[nf][3] = 0.f; }

    #pragma unroll
    for (int kt = 0; kt < 4; kt++) {
        int k0 = kt * 16 + q4 * 2;
        unsigned ah0 = *(const unsigned*)(Ah + ar * ASTR + k0);
        unsigned ah1 = *(const unsigned*)(Ah + (ar + 8) * ASTR + k0);
        unsigned ah2 = *(const unsigned*)(Ah + ar * ASTR + k0 + 8);
        unsigned ah3 = *(const unsigned*)(Ah + (ar + 8) * ASTR + k0 + 8);
        unsigned al0 = *(const unsigned*)(Al + ar * ASTR + k0);
        unsigned al1 = *(const unsigned*)(Al + (ar + 8) * ASTR + k0);
        unsigned al2 = *(const unsigned*)(Al + ar * ASTR + k0 + 8);
        unsigned al3 = *(const unsigned*)(Al + (ar + 8) * ASTR + k0 + 8);
        #pragma unroll
        for (int nf = 0; nf < 16; nf++) {
            int n = nf * 8 + g;
            unsigned bh0 = *(const unsigned*)(Bh + n * ASTR + k0);
            unsigned bh1 = *(const unsigned*)(Bh + n * ASTR + k0 + 8);
            unsigned bl0 = *(const unsigned*)(Bl + n * ASTR + k0);
            unsigned bl1 = *(const unsigned*)(Bl + n * ASTR + k0 + 8);
            mma_bf16(C[nf], ah0, ah1, ah2, ah3, bh0, bh1);   // hi*hi
            mma_bf16(C[nf], ah0, ah1, ah2, ah3, bl0, bl1);   // hi*lo
            mma_bf16(C[nf], al0, al1, al2, al3, bh0, bh1);   // lo*hi
        }
    }
    __syncthreads();   // all warps done reading A/B -> Hs may overwrite

    // epilogue: + ue_proj[src] (gather), relu, stage to smem
    {
        int s0 = s_src[ar], s1 = s_src[ar + 8];
        const float* up0 = g_ueproj + (size_t)s0 * HH;
        const float* up1 = g_ueproj + (size_t)s1 * HH;
        #pragma unroll
        for (int nf = 0; nf < 16; nf++) {
            int c0 = nf * 8 + q4 * 2;
            float2 u0 = *(const float2*)(up0 + c0);
            float2 u1 = *(const float2*)(up1 + c0);
            float2 v0, v1;
            v0.x = fmaxf(C[nf][0] + u0.x, 0.f);
            v0.y = fmaxf(C[nf][1] + u0.y, 0.f);
            v1.x = fmaxf(C[nf][2] + u1.x, 0.f);
            v1.y = fmaxf(C[nf][3] + u1.y, 0.f);
            *(float2*)(Hs + ar * 132 + c0) = v0;
            *(float2*)(Hs + (ar + 8) * 132 + c0) = v1;
        }
    }
    __syncthreads();

    // segmented reduce over sorted dst (two 64-row halves), few atomics
    {
        int c = t & 127, half = t >> 7;
        int r0 = half * 64;
        float acc = 0.f;
        int prev = s_dst[r0];
        for (int i = 0; i < 64; i++) {
            int r = r0 + i;
            int d = s_dst[r];
            if (d != prev) {
                atomicAdd(&g_agg[(size_t)prev * HH + c], acc);
                acc = 0.f; prev = d;
            }
            acc += Hs[r * 132 + c];
        }
        atomicAdd(&g_agg[(size_t)prev * HH + c], acc);
    }
}

// ---------------- final AP MLP: agg@W1b + deg*b1b, concat, mlp2 ------------
__global__ void __launch_bounds__(128) k_final(
    const float* __restrict__ ap_hid,
    const float* __restrict__ W1b, const float* __restrict__ b1b,
    const float* __restrict__ W2a, const float* __restrict__ b2a,
    const float* __restrict__ W2b, const float* __restrict__ b2b,
    float* __restrict__ out)
{
    __shared__ float Ss[16][128];
    __shared__ float Zs[16][192];
    __shared__ float Ys[16][128];
    __shared__ float sdeg[16];

    int t = threadIdx.x;
    int a0 = blockIdx.x * 16;

    for (int i = t; i < 16 * 128; i += 128)
        Ss[i >> 7][i & 127] = g_agg[(size_t)a0 * HH + i];
    if (t < 16) sdeg[t] = (float)g_cnt[a0 + t];
    for (int i = t; i < 16 * 64; i += 128)
        Zs[i >> 6][i & 63] = ap_hid[(size_t)a0 * DD + i];
    __syncthreads();

    // stage 1: Zs[r][64+c] = deg[r]*b1b[c] + sum_k Ss[r][k]*W1b[k][c]
    {
        int c = t;
        float acc[16];
        float bb = b1b[c];
        #pragma unroll
        for (int r = 0; r < 16; r++) acc[r] = sdeg[r] * bb;
        for (int k = 0; k < 128; k++) {
            float wv = W1b[k * HH + c];
            #pragma unroll
            for (int r = 0; r < 16; r++) acc[r] += Ss[r][k] * wv;
        }
        #pragma unroll
        for (int r = 0; r < 16; r++) Zs[r][64 + c] = acc[r];
    }
    __syncthreads();

    // stage 2: Ys = relu(Zs @ W2a + b2a)
    {
        int c = t;
        float acc[16];
        float bb = b2a[c];
        #pragma unroll
        for (int r = 0; r < 16; r++) acc[r] = bb;
        for (int k = 0; k < 192; k++) {
            float wv = W2a[k * HH + c];
            #pragma unroll
            for (int r = 0; r < 16; r++) acc[r] += Zs[r][k] * wv;
        }
        #pragma unroll
        for (int r = 0; r < 16; r++) Ys[r][c] = fmaxf(acc[r], 0.f);
    }
    __syncthreads();

    // stage 3: out = Ys @ W2b + b2b   (c = t&63, rows (t>>6)*8 .. +8)
    {
        int c = t & 63, rg = t >> 6;
        float acc[8];
        float bb = b2b[c];
        #pragma unroll
        for (int j = 0; j < 8; j++) acc[j] = bb;
        for (int k = 0; k < 128; k++) {
            float wv = W2b[k * DD + c];
            #pragma unroll
            for (int j = 0; j < 8; j++) acc[j] += Ys[rg * 8 + j][k] * wv;
        }
        #pragma unroll
        for (int j = 0; j < 8; j++)
            out[(size_t)(a0 + rg * 8 + j) * DD + c] = acc[j];
    }
}

// ---------------- launch ----------------------------------------------------
extern "C" void kernel_launch(void* const* d_in, const int* in_sizes, int n_in,
                              void* d_out, int out_size) {
    const float* ue_hid   = (const float*)d_in[0];
    const float* ap_hid   = (const float*)d_in[1];
    const float* edge_hid = (const float*)d_in[2];
    const int*   src      = (const int*)d_in[3];
    const int*   dst      = (const int*)d_in[4];
    const float* W1a      = (const float*)d_in[5];
    const float* b1a      = (const float*)d_in[6];
    const float* W1b      = (const float*)d_in[7];
    const float* b1b      = (const float*)d_in[8];
    const float* W2a      = (const float*)d_in[9];
    const float* b2a      = (const float*)d_in[10];
    const float* W2b      = (const float*)d_in[11];
    const float* b2b      = (const float*)d_in[12];
    float* out = (float*)d_out;

    cudaFuncSetAttribute(k_main, cudaFuncAttributeMaxDynamicSharedMemorySize, SMEM_MAIN);

    k_zero<<<5000, 256>>>();
    k_hist<<<(N_E + 255) / 256, 256>>>(dst);
    k_scan<<<1, 1024>>>();
    k_scatter<<<(N_E + 255) / 256, 256>>>(src, dst);
    k_prep_w<<<(HH * DD + 255) / 256, 256>>>(W1a);
    k_ueproj<<<(N_UE + 63) / 64, 256>>>(ue_hid, W1a, b1a);
    k_main<<<N_E / 128, 256, SMEM_MAIN>>>(edge_hid);
    k_final<<<N_AP / 16, 128>>>(ap_hid, W1b, b1b, W2a, b2a, W2b, b2b, out);
}